// round 13
// baseline (speedup 1.0000x reference)
#include <cuda_runtime.h>

#define W 512
#define H 512
#define BATCH 2
#define HW (H*W)
#define NCV (BATCH*(H-1)*W)
#define NCH (BATCH*H*(W-1))
#define L_STEP 0.24f
#define KK 0.0009f   /* 0.03*0.03 */

#define TW 128
#define TH 64
#define HALO 12
#define TSX (TW - 2*HALO)   /* 104 interior width  */
#define TSY (TH - 2*HALO)   /* 40  interior height */
#define NBX 5               /* ceil(512/104) */
#define NBY 13              /* ceil(512/40)  */
#define NTI 32              /* lanes (x), 4 px each */
#define NTJ 16              /* warp-rows (y), 4 px each */
#define NTHREADS (NTI*NTJ)  /* 512 */
#define NCTAS (NBX*NBY*BATCH)   /* 130 <= 148 SMs: co-resident, grid barrier safe */
#define NPH 42                  /* 41*12 + 8 = 500 steps */
#define FLAG_STRIDE 32          /* 128B apart: no same-line write serialization */

typedef unsigned long long ull;

/* scratch state (ping-pong) + premultiplied conductances + barrier flags */
__device__ float g_I0[BATCH*HW];
__device__ float g_I1[BATCH*HW];
__device__ float g_cvL[NCV];
__device__ float g_chL[NCH];
__device__ unsigned g_flags[NCTAS*FLAG_STRIDE];

/* ---- packed f32x2 helpers; psub is EXACT ((-1)*b exact, one .rn round) ---- */
__device__ __forceinline__ ull pk2(float lo, float hi) {
    ull r; unsigned a = __float_as_uint(lo), b = __float_as_uint(hi);
    asm("mov.b64 %0, {%1, %2};" : "=l"(r) : "r"(a), "r"(b));
    return r;
}
__device__ __forceinline__ void upk2(ull v, float& lo, float& hi) {
    unsigned a, b;
    asm("mov.b64 {%0, %1}, %2;" : "=r"(a), "=r"(b) : "l"(v));
    lo = __uint_as_float(a); hi = __uint_as_float(b);
}
__device__ __forceinline__ ull padd(ull a, ull b) {
    ull d; asm("add.rn.f32x2 %0, %1, %2;" : "=l"(d) : "l"(a), "l"(b)); return d;
}
__device__ __forceinline__ ull pmul(ull a, ull b) {
    ull d; asm("mul.rn.f32x2 %0, %1, %2;" : "=l"(d) : "l"(a), "l"(b)); return d;
}
__device__ __forceinline__ ull pfma(ull a, ull b, ull c) {
    ull d; asm("fma.rn.f32x2 %0, %1, %2, %3;" : "=l"(d) : "l"(a), "l"(b), "l"(c)); return d;
}
#define NEG1 0xBF800000BF800000ULL
__device__ __forceinline__ ull psub(ull a, ull b) { return pfma(NEG1, b, a); }

/* ---- conductance kernels: raw g to d_out region, L*g to scratch ---- */
__global__ void k_coeff_v(const float* __restrict__ guide, float* __restrict__ out_cv) {
    int idx = blockIdx.x*blockDim.x + threadIdx.x;
    if (idx >= NCV) return;
    int x = idx % W;
    int y = (idx / W) % (H-1);
    int b = idx / (W*(H-1));
    const float* gb = guide + (size_t)b*3*HW + (size_t)y*W + x;
    float s = 0.f;
    #pragma unroll
    for (int c = 0; c < 3; c++) s += fabsf(gb[(size_t)c*HW + W] - gb[(size_t)c*HW]);
    float m = s * (1.0f/3.0f);
    float g = 1.0f / (1.0f + (m*m)/KK);
    out_cv[idx] = g;
    g_cvL[idx]  = L_STEP * g;
}

__global__ void k_coeff_h(const float* __restrict__ guide, float* __restrict__ out_ch) {
    int idx = blockIdx.x*blockDim.x + threadIdx.x;
    if (idx >= NCH) return;
    int x = idx % (W-1);
    int y = (idx / (W-1)) % H;
    int b = idx / ((W-1)*H);
    const float* gb = guide + (size_t)b*3*HW + (size_t)y*W + x;
    float s = 0.f;
    #pragma unroll
    for (int c = 0; c < 3; c++) s += fabsf(gb[(size_t)c*HW + 1] - gb[(size_t)c*HW]);
    float m = s * (1.0f/3.0f);
    float g = 1.0f / (1.0f + (m*m)/KK);
    out_ch[idx] = g;
    g_chL[idx]  = L_STEP * g;
}

__global__ void k_reset() {
    int idx = blockIdx.x*blockDim.x + threadIdx.x;
    if (idx < NCTAS) g_flags[idx*FLAG_STRIDE] = 0u;
}

__device__ __forceinline__ void flag_store_release(unsigned* p, unsigned v) {
    asm volatile("st.release.gpu.u32 [%0], %1;" :: "l"(p), "r"(v) : "memory");
}
__device__ __forceinline__ unsigned flag_load_acquire(const unsigned* p) {
    unsigned v;
    asm volatile("ld.acquire.gpu.u32 %0, [%1];" : "=r"(v) : "l"(p) : "memory");
    return v;
}

/* software grid barrier: all NCTAS CTAs co-resident (1 CTA/SM, 130<=148). */
__device__ __forceinline__ void grid_barrier(int cta, unsigned target) {
    __syncthreads();
    if (threadIdx.x == 0) flag_store_release(&g_flags[cta*FLAG_STRIDE], target);
    if (threadIdx.x < NCTAS) {
        while (flag_load_acquire(&g_flags[threadIdx.x*FLAG_STRIDE]) < target) {
            __nanosleep(32);
        }
    }
    __syncthreads();
}

/* ---- persistent temporal-blocked diffusion, packed f32x2 flux form ----
 * State: 4 rows x 2 column-pairs per thread (P[4][2], f32x2). Flux form
 * (I - f_r) + f_{r+1}, f = c*d, with psub exact -> rounding sequence is
 * IDENTICAL to the validated scalar kernels (rel_err 8.2e-7 expected).
 * Pre-barrier: STS, shuffles, all diffs, horizontal + interior vertical
 * fluxes + shifted-flux repack (alu movs). Post-barrier: edge fluxes and
 * packed combines only. One __syncthreads per step (double-buffered rows).
 * Every 12 steps: interior write, grid barrier, reload (halo threads only). */
__global__ void __launch_bounds__(NTHREADS, 1)
k_persist(const float* __restrict__ initial, float* __restrict__ out_y) {
    __shared__ float sTop[2][NTJ][TW];
    __shared__ float sBot[2][NTJ][TW];

    const int tid = threadIdx.x;
    const int ti  = tid & 31;
    const int tj  = tid >> 5;
    const int bx = blockIdx.x, by = blockIdx.y, b = blockIdx.z;
    const int cta = bx + NBX*(by + NBY*b);

    const int ox  = bx*TSX - HALO;
    const int oy  = by*TSY - HALO;
    const int lx0 = ti*4, ly0 = tj*4;
    const int gx0 = ox + lx0;
    const int gy0 = oy + ly0;
    const bool xok = (gx0 >= 0) && (gx0 + 4 <= W);
    const bool skipReload = (lx0 >= HALO) && (lx0 + 4 <= TW - HALO) &&
                            (ly0 >= HALO) && (ly0 + 4 <= TH - HALO);

    const float* __restrict__ cvb = g_cvL + (size_t)b*(H-1)*W;
    const float* __restrict__ chb = g_chL + (size_t)b*H*(W-1);

    /* packed persistent coefficients */
    ull CVP[5][2];
    #pragma unroll
    for (int jj = 0; jj < 5; jj++) {
        int r = gy0 - 1 + jj;
        if (xok && r >= 0 && r < H-1) {
            ulonglong2 v = *(const ulonglong2*)(cvb + (size_t)r*W + gx0);
            CVP[jj][0] = v.x; CVP[jj][1] = v.y;
        } else { CVP[jj][0] = 0ull; CVP[jj][1] = 0ull; }
    }
    ull CHP[4][2]; float ch4[4];
    #pragma unroll
    for (int j = 0; j < 4; j++) {
        int gy = gy0 + j;
        float c[5];
        #pragma unroll
        for (int ii = 0; ii < 5; ii++) {
            int cc = gx0 - 1 + ii;
            c[ii] = (gy >= 0 && gy < H && cc >= 0 && cc < W-1)
                  ? chb[(size_t)gy*(W-1) + cc] : 0.f;
        }
        CHP[j][0] = pk2(c[0], c[1]);
        CHP[j][1] = pk2(c[2], c[3]);
        ch4[j] = c[4];
    }

    /* initial state as packed pairs */
    ull P[4][2];
    {
        const float* __restrict__ srcb = initial + (size_t)b*HW;
        #pragma unroll
        for (int j = 0; j < 4; j++) {
            int gy = gy0 + j;
            if (xok && gy >= 0 && gy < H) {
                ulonglong2 v = *(const ulonglong2*)(srcb + (size_t)gy*W + gx0);
                P[j][0] = v.x; P[j][1] = v.y;
            } else { P[j][0] = 0ull; P[j][1] = 0ull; }
        }
    }

    for (int p = 0; p < NPH; p++) {
        const int nsteps = (p == NPH-1) ? (500 - (NPH-1)*HALO) : HALO;
        for (int s = 0; s < nsteps; s++) {
            const int bs = s & 1;

            /* --- pre-barrier --- */
            *(ulonglong2*)&sTop[bs][tj][lx0] = make_ulonglong2(P[0][0], P[0][1]);
            *(ulonglong2*)&sBot[bs][tj][lx0] = make_ulonglong2(P[3][0], P[3][1]);

            float i0[4], i1[4], i2[4], i3[4];
            #pragma unroll
            for (int j = 0; j < 4; j++) {
                upk2(P[j][0], i0[j], i1[j]);
                upk2(P[j][1], i2[j], i3[j]);
            }
            float lf[4], rt[4];
            #pragma unroll
            for (int j = 0; j < 4; j++) {
                lf[j] = __shfl_up_sync  (0xffffffffu, i3[j], 1);
                rt[j] = __shfl_down_sync(0xffffffffu, i0[j], 1);
            }

            /* horizontal fluxes (packed) + shifted-flux pairs */
            ull FH0[4], FH1[4], FS0[4], FS1[4];
            #pragma unroll
            for (int j = 0; j < 4; j++) {
                ull D01 = psub(P[j][0], pk2(lf[j], i0[j]));   /* (I0-lf, I1-I0) */
                ull D23 = psub(P[j][1], pk2(i1[j], i2[j]));   /* (I2-I1, I3-I2) */
                float g4 = rt[j] - i3[j];
                FH0[j] = pmul(CHP[j][0], D01);                /* (f0, f1) */
                FH1[j] = pmul(CHP[j][1], D23);                /* (f2, f3) */
                float f4 = ch4[j] * g4;
                float f0s, f1s, f2s, f3s;
                upk2(FH0[j], f0s, f1s);
                upk2(FH1[j], f2s, f3s);
                FS0[j] = pk2(f1s, f2s);                       /* (f1, f2) */
                FS1[j] = pk2(f3s, f4);                        /* (f3, f4) */
            }
            /* interior vertical fluxes (packed) */
            ull FV1[2], FV2[2], FV3[2];
            #pragma unroll
            for (int q = 0; q < 2; q++) {
                FV1[q] = pmul(CVP[1][q], psub(P[1][q], P[0][q]));
                FV2[q] = pmul(CVP[2][q], psub(P[2][q], P[1][q]));
                FV3[q] = pmul(CVP[3][q], psub(P[3][q], P[2][q]));
            }

            __syncthreads();

            /* --- post-barrier: edge fluxes + combines --- */
            ull U[2], D[2];
            {
                ulonglong2 u = (tj > 0)     ? *(ulonglong2*)&sBot[bs][tj-1][lx0]
                                            : make_ulonglong2(0ull, 0ull);
                ulonglong2 d = (tj < NTJ-1) ? *(ulonglong2*)&sTop[bs][tj+1][lx0]
                                            : make_ulonglong2(0ull, 0ull);
                U[0]=u.x; U[1]=u.y; D[0]=d.x; D[1]=d.y;
            }

            ull N[4][2];
            #pragma unroll
            for (int q = 0; q < 2; q++) {
                ull FV0 = pmul(CVP[0][q], psub(P[0][q], U[q]));
                ull FV4 = pmul(CVP[4][q], psub(D[q],    P[3][q]));
                N[0][q] = padd(psub(P[0][q], FV0),    FV1[q]);
                N[1][q] = padd(psub(P[1][q], FV1[q]), FV2[q]);
                N[2][q] = padd(psub(P[2][q], FV2[q]), FV3[q]);
                N[3][q] = padd(psub(P[3][q], FV3[q]), FV4);
            }
            #pragma unroll
            for (int j = 0; j < 4; j++) {
                P[j][0] = padd(psub(N[j][0], FH0[j]), FS0[j]);
                P[j][1] = padd(psub(N[j][1], FH1[j]), FS1[j]);
            }
        }

        /* write interior: last phase straight to output, else ping-pong */
        float* __restrict__ wb = (p == NPH-1)
            ? (out_y + (size_t)b*HW)
            : (((p & 1) ? g_I0 : g_I1) + (size_t)b*HW);
        if (xok && lx0 >= HALO && lx0 < TW - HALO) {
            #pragma unroll
            for (int j = 0; j < 4; j++) {
                int ly = ly0 + j;
                int gy = gy0 + j;
                if (ly >= HALO && ly < TH - HALO && gy < H) {
                    *(ulonglong2*)(wb + (size_t)gy*W + gx0) =
                        make_ulonglong2(P[j][0], P[j][1]);
                }
            }
        }

        if (p < NPH-1) {
            grid_barrier(cta, (unsigned)(p + 1));
            if (!skipReload) {
                const float* __restrict__ rb = ((p & 1) ? g_I0 : g_I1) + (size_t)b*HW;
                #pragma unroll
                for (int j = 0; j < 4; j++) {
                    int gy = gy0 + j;
                    if (xok && gy >= 0 && gy < H) {
                        ulonglong2 v = *(const ulonglong2*)(rb + (size_t)gy*W + gx0);
                        P[j][0] = v.x; P[j][1] = v.y;
                    } else { P[j][0] = 0ull; P[j][1] = 0ull; }
                }
            }
        }
    }
}

extern "C" void kernel_launch(void* const* d_in, const int* in_sizes, int n_in,
                              void* d_out, int out_size) {
    const float* a0 = (const float*)d_in[0];
    const float* a1 = (const float*)d_in[1];
    const float* guide = a0;
    const float* initial = a1;
    if (n_in >= 2 && in_sizes[0] < in_sizes[1]) { guide = a1; initial = a0; }

    float* out    = (float*)d_out;
    float* out_y  = out;                       /* [BATCH*HW]   */
    float* out_cv = out + BATCH*HW;            /* [NCV]        */
    float* out_ch = out_cv + NCV;              /* [NCH]        */

    k_reset<<<1, 256>>>();
    k_coeff_v<<<(NCV + 255)/256, 256>>>(guide, out_cv);
    k_coeff_h<<<(NCH + 255)/256, 256>>>(guide, out_ch);

    dim3 grid(NBX, NBY, BATCH);
    k_persist<<<grid, NTHREADS>>>(initial, out_y);
}

// round 14
// speedup vs baseline: 1.1232x; 1.1232x over previous
#include <cuda_runtime.h>

#define W 512
#define H 512
#define BATCH 2
#define HW (H*W)
#define NCV (BATCH*(H-1)*W)
#define NCH (BATCH*H*(W-1))
#define L_STEP 0.24f
#define KK 0.0009f   /* 0.03*0.03 */

#define TW 128
#define TH 64
#define HALO 12
#define TSX (TW - 2*HALO)   /* 104 interior width  */
#define TSY (TH - 2*HALO)   /* 40  interior height */
#define NBX 5               /* ceil(512/104) */
#define NBY 13              /* ceil(512/40)  */
#define NTI 32              /* lanes (x), 4 px each */
#define NTJ 16              /* warp-rows (y), 4 px each */
#define NTHREADS (NTI*NTJ)  /* 512 */
#define NCTAS (NBX*NBY*BATCH)   /* 130 <= 148 SMs: co-resident, sync safe */
#define NPH 42                  /* 41*12 + 8 = 500 steps */
#define FLAG_STRIDE 32          /* 128B apart: no same-line write serialization */

/* scratch state (ping-pong) + premultiplied conductances + sync flags */
__device__ float g_I0[BATCH*HW];
__device__ float g_I1[BATCH*HW];
__device__ float g_cvL[NCV];
__device__ float g_chL[NCH];
__device__ unsigned g_flags[NCTAS*FLAG_STRIDE];

/* ---- conductance kernels: raw g to d_out region, L*g to scratch ---- */
__global__ void k_coeff_v(const float* __restrict__ guide, float* __restrict__ out_cv) {
    int idx = blockIdx.x*blockDim.x + threadIdx.x;
    if (idx >= NCV) return;
    int x = idx % W;
    int y = (idx / W) % (H-1);
    int b = idx / (W*(H-1));
    const float* gb = guide + (size_t)b*3*HW + (size_t)y*W + x;
    float s = 0.f;
    #pragma unroll
    for (int c = 0; c < 3; c++) s += fabsf(gb[(size_t)c*HW + W] - gb[(size_t)c*HW]);
    float m = s * (1.0f/3.0f);
    float g = 1.0f / (1.0f + (m*m)/KK);
    out_cv[idx] = g;
    g_cvL[idx]  = L_STEP * g;
}

__global__ void k_coeff_h(const float* __restrict__ guide, float* __restrict__ out_ch) {
    int idx = blockIdx.x*blockDim.x + threadIdx.x;
    if (idx >= NCH) return;
    int x = idx % (W-1);
    int y = (idx / (W-1)) % H;
    int b = idx / ((W-1)*H);
    const float* gb = guide + (size_t)b*3*HW + (size_t)y*W + x;
    float s = 0.f;
    #pragma unroll
    for (int c = 0; c < 3; c++) s += fabsf(gb[(size_t)c*HW + 1] - gb[(size_t)c*HW]);
    float m = s * (1.0f/3.0f);
    float g = 1.0f / (1.0f + (m*m)/KK);
    out_ch[idx] = g;
    g_chL[idx]  = L_STEP * g;
}

__global__ void k_reset() {
    int idx = blockIdx.x*blockDim.x + threadIdx.x;
    if (idx < NCTAS) g_flags[idx*FLAG_STRIDE] = 0u;
}

__device__ __forceinline__ void flag_store_release(unsigned* p, unsigned v) {
    asm volatile("st.release.gpu.u32 [%0], %1;" :: "l"(p), "r"(v) : "memory");
}
__device__ __forceinline__ unsigned flag_load_acquire(const unsigned* p) {
    unsigned v;
    asm volatile("ld.acquire.gpu.u32 %0, [%1];" : "=r"(v) : "l"(p) : "memory");
    return v;
}

/* Neighbor-only inter-CTA sync. A CTA's halo reload reads only the 3x3 tile
 * neighborhood (HALO < TSX,TSY), so after publishing its interior (flag =
 * target, release) it waits only for its <=8 neighbors to reach the same
 * phase. Skew-1 safety with the 2-buffer ping-pong: a neighbor overwrites
 * the buffer I'm reading (phase target+1, same parity) only after passing
 * its own wait on MY flag >= target+1, which I publish only after this
 * reload completes. All 130 CTAs are co-resident (1 CTA/SM) -> progress.
 * Tight spin (8 threads, distinct L2 lines), no nanosleep wake latency. */
__device__ __forceinline__ void neighbor_sync(int bx, int by, int b, int cta,
                                              unsigned target) {
    __syncthreads();   /* all interior STGs done */
    if (threadIdx.x == 0) flag_store_release(&g_flags[cta*FLAG_STRIDE], target);
    if (threadIdx.x < 9 && threadIdx.x != 4) {
        int dx = (int)threadIdx.x % 3 - 1;
        int dy = (int)threadIdx.x / 3 - 1;
        int nx = bx + dx, ny = by + dy;
        if (nx >= 0 && nx < NBX && ny >= 0 && ny < NBY) {
            int nc = nx + NBX*(ny + NBY*b);
            while (flag_load_acquire(&g_flags[nc*FLAG_STRIDE]) < target) { }
        }
    }
    __syncthreads();   /* neighbor completion observed by whole CTA */
}

/* ---- persistent temporal-blocked diffusion (validated R7 body) ----
 * 16 warp-rows x 32 lanes, 4x4 px/thread, fused-FMA update. Per step:
 * publish boundary rows (double-buffered), shuffles + all pre-computable
 * diffs BEFORE one __syncthreads; edge fluxes + combines after.
 * Every 12 steps: interior write, neighbor sync, reload (halo threads). */
__global__ void __launch_bounds__(NTHREADS, 1)
k_persist(const float* __restrict__ initial, float* __restrict__ out_y) {
    __shared__ float sTop[2][NTJ][TW];
    __shared__ float sBot[2][NTJ][TW];

    const int tid = threadIdx.x;
    const int ti  = tid & 31;
    const int tj  = tid >> 5;
    const int bx = blockIdx.x, by = blockIdx.y, b = blockIdx.z;
    const int cta = bx + NBX*(by + NBY*b);

    const int ox  = bx*TSX - HALO;
    const int oy  = by*TSY - HALO;
    const int lx0 = ti*4, ly0 = tj*4;
    const int gx0 = ox + lx0;
    const int gy0 = oy + ly0;
    const bool xok = (gx0 >= 0) && (gx0 + 4 <= W);
    const bool skipReload = (lx0 >= HALO) && (lx0 + 4 <= TW - HALO) &&
                            (ly0 >= HALO) && (ly0 + 4 <= TH - HALO);

    const float* __restrict__ cvb = g_cvL + (size_t)b*(H-1)*W;
    const float* __restrict__ chb = g_chL + (size_t)b*H*(W-1);

    float CV[5][4];
    #pragma unroll
    for (int jj = 0; jj < 5; jj++) {
        int r = gy0 - 1 + jj;
        if (xok && r >= 0 && r < H-1) {
            float4 v = *(const float4*)(cvb + (size_t)r*W + gx0);
            CV[jj][0]=v.x; CV[jj][1]=v.y; CV[jj][2]=v.z; CV[jj][3]=v.w;
        } else {
            CV[jj][0]=0.f; CV[jj][1]=0.f; CV[jj][2]=0.f; CV[jj][3]=0.f;
        }
    }
    float CH[4][5];
    #pragma unroll
    for (int j = 0; j < 4; j++) {
        int gy = gy0 + j;
        #pragma unroll
        for (int ii = 0; ii < 5; ii++) {
            int c = gx0 - 1 + ii;
            CH[j][ii] = (gy >= 0 && gy < H && c >= 0 && c < W-1)
                      ? chb[(size_t)gy*(W-1) + c] : 0.f;
        }
    }

    float I[4][4];
    {
        const float* __restrict__ srcb = initial + (size_t)b*HW;
        #pragma unroll
        for (int j = 0; j < 4; j++) {
            int gy = gy0 + j;
            if (xok && gy >= 0 && gy < H) {
                float4 v = *(const float4*)(srcb + (size_t)gy*W + gx0);
                I[j][0]=v.x; I[j][1]=v.y; I[j][2]=v.z; I[j][3]=v.w;
            } else {
                I[j][0]=0.f; I[j][1]=0.f; I[j][2]=0.f; I[j][3]=0.f;
            }
        }
    }

    for (int p = 0; p < NPH; p++) {
        const int nsteps = (p == NPH-1) ? (500 - (NPH-1)*HALO) : HALO;
        for (int s = 0; s < nsteps; s++) {
            const int bs = s & 1;

            /* publish boundary rows first */
            *(float4*)&sTop[bs][tj][lx0] = make_float4(I[0][0],I[0][1],I[0][2],I[0][3]);
            *(float4*)&sBot[bs][tj][lx0] = make_float4(I[3][0],I[3][1],I[3][2],I[3][3]);

            /* pre-barrier independent work */
            float lf[4], rt[4];
            #pragma unroll
            for (int j = 0; j < 4; j++) {
                lf[j] = __shfl_up_sync  (0xffffffffu, I[j][3], 1);
                rt[j] = __shfl_down_sync(0xffffffffu, I[j][0], 1);
            }
            float DH[4][5];
            #pragma unroll
            for (int j = 0; j < 4; j++) {
                DH[j][0] = I[j][0] - lf[j];
                DH[j][1] = I[j][1] - I[j][0];
                DH[j][2] = I[j][2] - I[j][1];
                DH[j][3] = I[j][3] - I[j][2];
                DH[j][4] = rt[j]   - I[j][3];
            }
            float DV1[4], DV2[4], DV3[4];
            #pragma unroll
            for (int i = 0; i < 4; i++) {
                DV1[i] = I[1][i] - I[0][i];
                DV2[i] = I[2][i] - I[1][i];
                DV3[i] = I[3][i] - I[2][i];
            }

            __syncthreads();

            float4 upv = (tj > 0)     ? *(float4*)&sBot[bs][tj-1][lx0] : make_float4(0,0,0,0);
            float4 dnv = (tj < NTJ-1) ? *(float4*)&sTop[bs][tj+1][lx0] : make_float4(0,0,0,0);
            float up[4] = {upv.x, upv.y, upv.z, upv.w};
            float dn[4] = {dnv.x, dnv.y, dnv.z, dnv.w};

            float N_[4][4];
            #pragma unroll
            for (int i = 0; i < 4; i++) {
                float dv0 = I[0][i] - up[i];
                float dv4 = dn[i]   - I[3][i];
                N_[0][i] = fmaf(CV[1][i], DV1[i], fmaf(CV[0][i], -dv0,    I[0][i]));
                N_[1][i] = fmaf(CV[2][i], DV2[i], fmaf(CV[1][i], -DV1[i], I[1][i]));
                N_[2][i] = fmaf(CV[3][i], DV3[i], fmaf(CV[2][i], -DV2[i], I[2][i]));
                N_[3][i] = fmaf(CV[4][i], dv4,    fmaf(CV[3][i], -DV3[i], I[3][i]));
            }
            #pragma unroll
            for (int j = 0; j < 4; j++) {
                I[j][0] = fmaf(CH[j][1], DH[j][1], fmaf(CH[j][0], -DH[j][0], N_[j][0]));
                I[j][1] = fmaf(CH[j][2], DH[j][2], fmaf(CH[j][1], -DH[j][1], N_[j][1]));
                I[j][2] = fmaf(CH[j][3], DH[j][3], fmaf(CH[j][2], -DH[j][2], N_[j][2]));
                I[j][3] = fmaf(CH[j][4], DH[j][4], fmaf(CH[j][3], -DH[j][3], N_[j][3]));
            }
        }

        /* write interior: last phase straight to output, else ping-pong */
        float* __restrict__ wb = (p == NPH-1)
            ? (out_y + (size_t)b*HW)
            : (((p & 1) ? g_I0 : g_I1) + (size_t)b*HW);
        if (xok && lx0 >= HALO && lx0 < TW - HALO) {
            #pragma unroll
            for (int j = 0; j < 4; j++) {
                int ly = ly0 + j;
                int gy = gy0 + j;
                if (ly >= HALO && ly < TH - HALO && gy < H) {
                    *(float4*)(wb + (size_t)gy*W + gx0) =
                        make_float4(I[j][0], I[j][1], I[j][2], I[j][3]);
                }
            }
        }

        if (p < NPH-1) {
            neighbor_sync(bx, by, b, cta, (unsigned)(p + 1));
            if (!skipReload) {
                const float* __restrict__ rb = ((p & 1) ? g_I0 : g_I1) + (size_t)b*HW;
                #pragma unroll
                for (int j = 0; j < 4; j++) {
                    int gy = gy0 + j;
                    if (xok && gy >= 0 && gy < H) {
                        float4 v = *(const float4*)(rb + (size_t)gy*W + gx0);
                        I[j][0]=v.x; I[j][1]=v.y; I[j][2]=v.z; I[j][3]=v.w;
                    } else {
                        I[j][0]=0.f; I[j][1]=0.f; I[j][2]=0.f; I[j][3]=0.f;
                    }
                }
            }
        }
    }
}

extern "C" void kernel_launch(void* const* d_in, const int* in_sizes, int n_in,
                              void* d_out, int out_size) {
    const float* a0 = (const float*)d_in[0];
    const float* a1 = (const float*)d_in[1];
    const float* guide = a0;
    const float* initial = a1;
    if (n_in >= 2 && in_sizes[0] < in_sizes[1]) { guide = a1; initial = a0; }

    float* out    = (float*)d_out;
    float* out_y  = out;                       /* [BATCH*HW]   */
    float* out_cv = out + BATCH*HW;            /* [NCV]        */
    float* out_ch = out_cv + NCV;              /* [NCH]        */

    k_reset<<<1, 256>>>();
    k_coeff_v<<<(NCV + 255)/256, 256>>>(guide, out_cv);
    k_coeff_h<<<(NCH + 255)/256, 256>>>(guide, out_ch);

    dim3 grid(NBX, NBY, BATCH);
    k_persist<<<grid, NTHREADS>>>(initial, out_y);
}

// round 15
// speedup vs baseline: 1.2717x; 1.1322x over previous
#include <cuda_runtime.h>

#define W 512
#define H 512
#define BATCH 2
#define HW (H*W)
#define NCV (BATCH*(H-1)*W)
#define NCH (BATCH*H*(W-1))
#define L_STEP 0.24f
#define KK 0.0009f   /* 0.03*0.03 */

#define TW 128
#define TH 64
#define HALO 12
#define TSX (TW - 2*HALO)   /* 104 interior width  */
#define TSY (TH - 2*HALO)   /* 40  interior height */
#define NBX 5               /* ceil(512/104) */
#define NBY 13              /* ceil(512/40)  */
#define NTI 32              /* lanes (x), 4 px each */
#define NTJ 16              /* warp-rows (y), 4 px each */
#define NTHREADS (NTI*NTJ)  /* 512 */
#define NCTAS (NBX*NBY*BATCH)   /* 130 <= 148 SMs: co-resident, sync safe */
#define NPH 42                  /* 41*12 + 8 = 500 steps */
#define FLAG_STRIDE 32          /* 128B apart: no same-line write serialization */

/* scratch state (ping-pong) + premultiplied conductances + sync flags */
__device__ float g_I0[BATCH*HW];
__device__ float g_I1[BATCH*HW];
__device__ float g_cvL[NCV];
__device__ float g_chL[NCH];
__device__ unsigned g_flags[NCTAS*FLAG_STRIDE];

/* ---- conductance kernels: raw g to d_out region, L*g to scratch ---- */
__global__ void k_coeff_v(const float* __restrict__ guide, float* __restrict__ out_cv) {
    int idx = blockIdx.x*blockDim.x + threadIdx.x;
    if (idx >= NCV) return;
    int x = idx % W;
    int y = (idx / W) % (H-1);
    int b = idx / (W*(H-1));
    const float* gb = guide + (size_t)b*3*HW + (size_t)y*W + x;
    float s = 0.f;
    #pragma unroll
    for (int c = 0; c < 3; c++) s += fabsf(gb[(size_t)c*HW + W] - gb[(size_t)c*HW]);
    float m = s * (1.0f/3.0f);
    float g = 1.0f / (1.0f + (m*m)/KK);
    out_cv[idx] = g;
    g_cvL[idx]  = L_STEP * g;
}

__global__ void k_coeff_h(const float* __restrict__ guide, float* __restrict__ out_ch) {
    int idx = blockIdx.x*blockDim.x + threadIdx.x;
    if (idx >= NCH) return;
    int x = idx % (W-1);
    int y = (idx / (W-1)) % H;
    int b = idx / ((W-1)*H);
    const float* gb = guide + (size_t)b*3*HW + (size_t)y*W + x;
    float s = 0.f;
    #pragma unroll
    for (int c = 0; c < 3; c++) s += fabsf(gb[(size_t)c*HW + 1] - gb[(size_t)c*HW]);
    float m = s * (1.0f/3.0f);
    float g = 1.0f / (1.0f + (m*m)/KK);
    out_ch[idx] = g;
    g_chL[idx]  = L_STEP * g;
}

__global__ void k_reset() {
    int idx = blockIdx.x*blockDim.x + threadIdx.x;
    if (idx < NCTAS) g_flags[idx*FLAG_STRIDE] = 0u;
}

__device__ __forceinline__ void flag_store_release(unsigned* p, unsigned v) {
    asm volatile("st.release.gpu.u32 [%0], %1;" :: "l"(p), "r"(v) : "memory");
}
__device__ __forceinline__ unsigned flag_load_acquire(const unsigned* p) {
    unsigned v;
    asm volatile("ld.acquire.gpu.u32 %0, [%1];" : "=r"(v) : "l"(p) : "memory");
    return v;
}

/* Neighbor-only inter-CTA sync (validated R14): release my flag, 8 threads
 * tight-spin on the 3x3 tile neighborhood's flags. Skew-1 safe with the
 * 2-buffer ping-pong; all 130 CTAs co-resident -> progress. */
__device__ __forceinline__ void neighbor_sync(int bx, int by, int b, int cta,
                                              unsigned target) {
    __syncthreads();
    if (threadIdx.x == 0) flag_store_release(&g_flags[cta*FLAG_STRIDE], target);
    if (threadIdx.x < 9 && threadIdx.x != 4) {
        int dx = (int)threadIdx.x % 3 - 1;
        int dy = (int)threadIdx.x / 3 - 1;
        int nx = bx + dx, ny = by + dy;
        if (nx >= 0 && nx < NBX && ny >= 0 && ny < NBY) {
            int nc = nx + NBX*(ny + NBY*b);
            while (flag_load_acquire(&g_flags[nc*FLAG_STRIDE]) < target) { }
        }
    }
    __syncthreads();
}

/* ---- persistent temporal-blocked diffusion, Jacobi single-pass form ----
 * The reference reads dv AND dh from the same pre-update I, so one step is
 * the linear 5-point update
 *   I' = cm*I + cv_r*up + cv_{r+1}*dn + ch_c*lf + ch_{c+1}*rt,
 *   cm = 1 - cv_r - cv_{r+1} - ch_c - ch_{c+1}   (precomputed, registers).
 * Rows 1,2 of the 4x4 depend only on register values -> fully pre-barrier.
 * Rows 0,3: all but one FFMA pre-barrier; post-barrier = LDS -> 1 FFMA/px.
 * Full reassociation of a convex combination: rounding delta bounded ~1e-6
 * over 500 steps. Outside-image cells have all coeffs 0 -> cm=1 -> I'=I.
 * Every 12 steps: interior write, neighbor sync, reload (halo threads). */
__global__ void __launch_bounds__(NTHREADS, 1)
k_persist(const float* __restrict__ initial, float* __restrict__ out_y) {
    __shared__ float sTop[2][NTJ][TW];
    __shared__ float sBot[2][NTJ][TW];

    const int tid = threadIdx.x;
    const int ti  = tid & 31;
    const int tj  = tid >> 5;
    const int bx = blockIdx.x, by = blockIdx.y, b = blockIdx.z;
    const int cta = bx + NBX*(by + NBY*b);

    const int ox  = bx*TSX - HALO;
    const int oy  = by*TSY - HALO;
    const int lx0 = ti*4, ly0 = tj*4;
    const int gx0 = ox + lx0;
    const int gy0 = oy + ly0;
    const bool xok = (gx0 >= 0) && (gx0 + 4 <= W);
    const bool skipReload = (lx0 >= HALO) && (lx0 + 4 <= TW - HALO) &&
                            (ly0 >= HALO) && (ly0 + 4 <= TH - HALO);

    const float* __restrict__ cvb = g_cvL + (size_t)b*(H-1)*W;
    const float* __restrict__ chb = g_chL + (size_t)b*H*(W-1);

    /* persistent coefficients */
    float CV[5][4];   /* rows gy0-1 .. gy0+3 of L*cv */
    #pragma unroll
    for (int jj = 0; jj < 5; jj++) {
        int r = gy0 - 1 + jj;
        if (xok && r >= 0 && r < H-1) {
            float4 v = *(const float4*)(cvb + (size_t)r*W + gx0);
            CV[jj][0]=v.x; CV[jj][1]=v.y; CV[jj][2]=v.z; CV[jj][3]=v.w;
        } else {
            CV[jj][0]=0.f; CV[jj][1]=0.f; CV[jj][2]=0.f; CV[jj][3]=0.f;
        }
    }
    float CH[4][5];   /* cols gx0-1 .. gx0+3 of L*ch */
    #pragma unroll
    for (int j = 0; j < 4; j++) {
        int gy = gy0 + j;
        #pragma unroll
        for (int ii = 0; ii < 5; ii++) {
            int c = gx0 - 1 + ii;
            CH[j][ii] = (gy >= 0 && gy < H && c >= 0 && c < W-1)
                      ? chb[(size_t)gy*(W-1) + c] : 0.f;
        }
    }
    /* center weights: cm[j][i] = 1 - cv_up - cv_dn - ch_lf - ch_rt */
    float CM[4][4];
    #pragma unroll
    for (int j = 0; j < 4; j++) {
        #pragma unroll
        for (int i = 0; i < 4; i++) {
            CM[j][i] = 1.0f - CV[j][i] - CV[j+1][i] - CH[j][i] - CH[j][i+1];
        }
    }

    /* initial state straight from input */
    float I[4][4];
    {
        const float* __restrict__ srcb = initial + (size_t)b*HW;
        #pragma unroll
        for (int j = 0; j < 4; j++) {
            int gy = gy0 + j;
            if (xok && gy >= 0 && gy < H) {
                float4 v = *(const float4*)(srcb + (size_t)gy*W + gx0);
                I[j][0]=v.x; I[j][1]=v.y; I[j][2]=v.z; I[j][3]=v.w;
            } else {
                I[j][0]=0.f; I[j][1]=0.f; I[j][2]=0.f; I[j][3]=0.f;
            }
        }
    }

    for (int p = 0; p < NPH; p++) {
        const int nsteps = (p == NPH-1) ? (500 - (NPH-1)*HALO) : HALO;
        for (int s = 0; s < nsteps; s++) {
            const int bs = s & 1;

            /* publish boundary rows first (pre-update values) */
            *(float4*)&sTop[bs][tj][lx0] = make_float4(I[0][0],I[0][1],I[0][2],I[0][3]);
            *(float4*)&sBot[bs][tj][lx0] = make_float4(I[3][0],I[3][1],I[3][2],I[3][3]);

            float lf[4], rt[4];
            #pragma unroll
            for (int j = 0; j < 4; j++) {
                lf[j] = __shfl_up_sync  (0xffffffffu, I[j][3], 1);  /* lane0 garbage -> zero coeff */
                rt[j] = __shfl_down_sync(0xffffffffu, I[j][0], 1);  /* lane31 garbage -> zero coeff */
            }

            /* pre-barrier: horizontal+center accumulation for every pixel,
             * plus the in-register vertical neighbor terms */
            float A[4][4];
            #pragma unroll
            for (int j = 0; j < 4; j++) {
                A[j][0] = fmaf(CH[j][1], I[j][1], fmaf(CH[j][0], lf[j],   CM[j][0]*I[j][0]));
                A[j][1] = fmaf(CH[j][2], I[j][2], fmaf(CH[j][1], I[j][0], CM[j][1]*I[j][1]));
                A[j][2] = fmaf(CH[j][3], I[j][3], fmaf(CH[j][2], I[j][1], CM[j][2]*I[j][2]));
                A[j][3] = fmaf(CH[j][4], rt[j],   fmaf(CH[j][3], I[j][2], CM[j][3]*I[j][3]));
            }
            #pragma unroll
            for (int i = 0; i < 4; i++) {
                /* rows 1,2: both vertical neighbors in registers -> complete */
                A[1][i] = fmaf(CV[2][i], I[2][i], fmaf(CV[1][i], I[0][i], A[1][i]));
                A[2][i] = fmaf(CV[3][i], I[3][i], fmaf(CV[2][i], I[1][i], A[2][i]));
                /* rows 0,3: add the in-register vertical side only */
                A[0][i] = fmaf(CV[1][i], I[1][i], A[0][i]);
                A[3][i] = fmaf(CV[3][i], I[2][i], A[3][i]);
            }

            __syncthreads();

            /* post-barrier: one FFMA per edge pixel */
            float4 upv = (tj > 0)     ? *(float4*)&sBot[bs][tj-1][lx0] : make_float4(0,0,0,0);
            float4 dnv = (tj < NTJ-1) ? *(float4*)&sTop[bs][tj+1][lx0] : make_float4(0,0,0,0);
            float up[4] = {upv.x, upv.y, upv.z, upv.w};
            float dn[4] = {dnv.x, dnv.y, dnv.z, dnv.w};

            #pragma unroll
            for (int i = 0; i < 4; i++) {
                I[0][i] = fmaf(CV[0][i], up[i], A[0][i]);
                I[1][i] = A[1][i];
                I[2][i] = A[2][i];
                I[3][i] = fmaf(CV[4][i], dn[i], A[3][i]);
            }
        }

        /* write interior: last phase straight to output, else ping-pong */
        float* __restrict__ wb = (p == NPH-1)
            ? (out_y + (size_t)b*HW)
            : (((p & 1) ? g_I0 : g_I1) + (size_t)b*HW);
        if (xok && lx0 >= HALO && lx0 < TW - HALO) {
            #pragma unroll
            for (int j = 0; j < 4; j++) {
                int ly = ly0 + j;
                int gy = gy0 + j;
                if (ly >= HALO && ly < TH - HALO && gy < H) {
                    *(float4*)(wb + (size_t)gy*W + gx0) =
                        make_float4(I[j][0], I[j][1], I[j][2], I[j][3]);
                }
            }
        }

        if (p < NPH-1) {
            neighbor_sync(bx, by, b, cta, (unsigned)(p + 1));
            if (!skipReload) {
                const float* __restrict__ rb = ((p & 1) ? g_I0 : g_I1) + (size_t)b*HW;
                #pragma unroll
                for (int j = 0; j < 4; j++) {
                    int gy = gy0 + j;
                    if (xok && gy >= 0 && gy < H) {
                        float4 v = *(const float4*)(rb + (size_t)gy*W + gx0);
                        I[j][0]=v.x; I[j][1]=v.y; I[j][2]=v.z; I[j][3]=v.w;
                    } else {
                        I[j][0]=0.f; I[j][1]=0.f; I[j][2]=0.f; I[j][3]=0.f;
                    }
                }
            }
        }
    }
}

extern "C" void kernel_launch(void* const* d_in, const int* in_sizes, int n_in,
                              void* d_out, int out_size) {
    const float* a0 = (const float*)d_in[0];
    const float* a1 = (const float*)d_in[1];
    const float* guide = a0;
    const float* initial = a1;
    if (n_in >= 2 && in_sizes[0] < in_sizes[1]) { guide = a1; initial = a0; }

    float* out    = (float*)d_out;
    float* out_y  = out;                       /* [BATCH*HW]   */
    float* out_cv = out + BATCH*HW;            /* [NCV]        */
    float* out_ch = out_cv + NCV;              /* [NCH]        */

    k_reset<<<1, 256>>>();
    k_coeff_v<<<(NCV + 255)/256, 256>>>(guide, out_cv);
    k_coeff_h<<<(NCH + 255)/256, 256>>>(guide, out_ch);

    dim3 grid(NBX, NBY, BATCH);
    k_persist<<<grid, NTHREADS>>>(initial, out_y);
}